// round 1
// baseline (speedup 1.0000x reference)
#include <cuda_runtime.h>
#include <math.h>

#define B_  16
#define H_  8
#define S_  1024
#define D_  64
#define D2_ 128

// ---------------- scratch (static device globals; no allocation) -------------
__device__ int2  g_pairs[B_ * S_];
__device__ float g_Qc[(size_t)B_ * H_ * S_ * D2_];
__device__ float g_Kc[(size_t)B_ * H_ * S_ * D2_];
__device__ float g_Vc[(size_t)B_ * H_ * S_ * D2_];
__device__ float g_O [(size_t)B_ * H_ * S_ * D2_];

// ---------------- kernel 1: IoU argmax pairs ---------------------------------
// grid: (16, B), block 256 (8 warps, 8 rows/warp)
__global__ void pairs_kernel(const float* __restrict__ centers) {
    __shared__ float sx1[S_], sy1[S_], sx2[S_], sy2[S_], sar[S_], sl1[S_];
    const int b = blockIdx.y;
    const float* c = centers + (size_t)b * S_ * 4;

    for (int i = threadIdx.x; i < S_; i += 256) {
        float cx = c[i * 4 + 0];
        float cy = c[i * 4 + 1];
        float hh = c[i * 4 + 2];   // h is index 2
        float ww = c[i * 4 + 3];   // w is index 3
        float x1 = cx - ww * 0.5f;
        float y1 = cy - hh * 0.5f;
        float x2 = cx + ww * 0.5f;
        float y2 = cy + hh * 0.5f;
        sx1[i] = x1; sy1[i] = y1; sx2[i] = x2; sy2[i] = y2;
        float dx = x2 - x1, dy = y2 - y1;
        sar[i] = dx * dy;                    // area from box diffs (matches ref)
        sl1[i] = fabsf(dx) + fabsf(dy);      // l1 from box diffs (matches ref)
    }
    __syncthreads();

    const int warp = threadIdx.x >> 5;
    const int lane = threadIdx.x & 31;
    const int rowbase = blockIdx.x * 64 + warp * 8;

    for (int r = 0; r < 8; r++) {
        const int i = rowbase + r;
        const float ax1 = sx1[i], ay1 = sy1[i], ax2 = sx2[i], ay2 = sy2[i], aa = sar[i];
        float best = -INFINITY;
        int   bidx = 0;
        for (int k = lane; k < S_; k += 32) {
            float xm = fmaxf(ax1, sx1[k]);
            float ym = fmaxf(ay1, sy1[k]);
            float xM = fminf(ax2, sx2[k]);
            float yM = fminf(ay2, sy2[k]);
            float inter = (xM - xm) * (yM - ym);         // NOT clamped (matches ref)
            float uni   = (aa + sar[k]) - inter;         // (a_i + a_k) - inter order
            float iou   = __fdiv_rn(inter, uni);         // IEEE div regardless of fast_math
            if (k == i) iou -= 1.0f;                     // - eye
            if (iou > best) { best = iou; bidx = k; }    // strict > keeps first occurrence
        }
        // warp argmax reduce; ties -> smaller index (jnp.argmax first-occurrence)
        for (int off = 16; off; off >>= 1) {
            float ov = __shfl_xor_sync(0xFFFFFFFFu, best, off);
            int   oi = __shfl_xor_sync(0xFFFFFFFFu, bidx, off);
            if (ov > best || (ov == best && oi < bidx)) { best = ov; bidx = oi; }
        }
        if (lane == 0) {
            int partner = bidx;
            int2 pr = (sl1[i] >= sl1[partner]) ? make_int2(i, partner)
                                               : make_int2(partner, i);
            g_pairs[b * S_ + i] = pr;
        }
    }
}

// ---------------- kernel 2: gather concat q/k/v ------------------------------
// one float4 of the 128-wide concat dim per thread
__global__ void gather_kernel(const float* __restrict__ Q,
                              const float* __restrict__ K,
                              const float* __restrict__ V) {
    size_t t = (size_t)blockIdx.x * 256 + threadIdx.x;   // B*H*S*32 total
    if (t >= (size_t)B_ * H_ * S_ * 32) return;
    int    d4  = (int)(t & 31);
    size_t bhs = t >> 5;                 // b*H*S + h*S + s
    int    s   = (int)(bhs & (S_ - 1));
    size_t bh  = bhs >> 10;              // b*H + h
    int    b   = (int)(bh >> 3);

    int2 pr = g_pairs[b * S_ + s];
    int  src = (d4 < 16) ? pr.x : pr.y;
    int  dd  = (d4 & 15) * 4;

    size_t srcoff = (bh * S_ + (size_t)src) * D_ + dd;
    size_t dst    = bhs * D2_ + (size_t)d4 * 4;

    *(float4*)(g_Qc + dst) = *(const float4*)(Q + srcoff);
    *(float4*)(g_Kc + dst) = *(const float4*)(K + srcoff);
    *(float4*)(g_Vc + dst) = *(const float4*)(V + srcoff);
}

// ---------------- kernel 3: fp32 flash attention -----------------------------
#define BM 64
#define BN 64
#define QP 129   // padded pitches to break bank conflicts
#define KP 129
#define VP 132
#define PP 65

__global__ void attn_kernel() {
    extern __shared__ float sm[];
    float* Qs = sm;                  // BM x QP
    float* Ks = Qs + BM * QP;        // BN x KP
    float* Vs = Ks + BN * KP;        // BN x VP
    float* Ps = Vs + BN * VP;        // BM x PP

    const int qb = blockIdx.x;       // 0..15
    const int bh = blockIdx.y;       // 0..127
    const float* Qg = g_Qc + ((size_t)bh * S_ + (size_t)qb * BM) * D2_;
    const float* Kg = g_Kc + (size_t)bh * S_ * D2_;
    const float* Vg = g_Vc + (size_t)bh * S_ * D2_;

    const int tid = threadIdx.x;
    const int tx = tid & 15, ty = tid >> 4;
    const int i0 = ty * 4;           // 4 q-rows per thread
    const int j0 = tx * 4;           // 4 k-cols per thread (for S)
    const int c0 = tx * 8;           // 8 out-cols per thread (for O)

    // load Q tile once
    for (int f = tid; f < BM * 32; f += 256) {
        int row = f >> 5, d4 = f & 31;
        float4 v = *(const float4*)(Qg + (size_t)row * D2_ + d4 * 4);
        float* p = Qs + row * QP + d4 * 4;
        p[0] = v.x; p[1] = v.y; p[2] = v.z; p[3] = v.w;
    }

    float m[4], l[4], o[4][8];
#pragma unroll
    for (int ii = 0; ii < 4; ii++) {
        m[ii] = -INFINITY; l[ii] = 0.f;
#pragma unroll
        for (int cc = 0; cc < 8; cc++) o[ii][cc] = 0.f;
    }

    for (int kt = 0; kt < S_ / BN; kt++) {
        __syncthreads();  // guard Ks/Vs/Ps reuse from previous iteration
        for (int f = tid; f < BN * 32; f += 256) {
            int row = f >> 5, d4 = f & 31;
            float4 kv = *(const float4*)(Kg + ((size_t)kt * BN + row) * D2_ + d4 * 4);
            float* kp = Ks + row * KP + d4 * 4;
            kp[0] = kv.x; kp[1] = kv.y; kp[2] = kv.z; kp[3] = kv.w;
            float4 vv = *(const float4*)(Vg + ((size_t)kt * BN + row) * D2_ + d4 * 4);
            float* vp = Vs + row * VP + d4 * 4;
            vp[0] = vv.x; vp[1] = vv.y; vp[2] = vv.z; vp[3] = vv.w;
        }
        __syncthreads();

        // ---- S = Q K^T (4x4 microtile) ----
        float acc[4][4];
#pragma unroll
        for (int ii = 0; ii < 4; ii++)
#pragma unroll
            for (int jj = 0; jj < 4; jj++) acc[ii][jj] = 0.f;

#pragma unroll 4
        for (int d = 0; d < D2_; d++) {
            float q0 = Qs[(i0 + 0) * QP + d];
            float q1 = Qs[(i0 + 1) * QP + d];
            float q2 = Qs[(i0 + 2) * QP + d];
            float q3 = Qs[(i0 + 3) * QP + d];
            float k0 = Ks[(j0 + 0) * KP + d];
            float k1 = Ks[(j0 + 1) * KP + d];
            float k2 = Ks[(j0 + 2) * KP + d];
            float k3 = Ks[(j0 + 3) * KP + d];
            acc[0][0] += q0 * k0; acc[0][1] += q0 * k1; acc[0][2] += q0 * k2; acc[0][3] += q0 * k3;
            acc[1][0] += q1 * k0; acc[1][1] += q1 * k1; acc[1][2] += q1 * k2; acc[1][3] += q1 * k3;
            acc[2][0] += q2 * k0; acc[2][1] += q2 * k1; acc[2][2] += q2 * k2; acc[2][3] += q2 * k3;
            acc[3][0] += q3 * k0; acc[3][1] += q3 * k1; acc[3][2] += q3 * k2; acc[3][3] += q3 * k3;
        }

        // ---- online softmax update ----
        float alpha[4];
#pragma unroll
        for (int ii = 0; ii < 4; ii++) {
            float mt = fmaxf(fmaxf(acc[ii][0], acc[ii][1]), fmaxf(acc[ii][2], acc[ii][3]));
#pragma unroll
            for (int off = 8; off; off >>= 1)
                mt = fmaxf(mt, __shfl_xor_sync(0xFFFFFFFFu, mt, off));
            float mn = fmaxf(m[ii], mt);
            alpha[ii] = __expf(m[ii] - mn);   // first tile: exp(-inf)=0
            m[ii] = mn;
        }
#pragma unroll
        for (int ii = 0; ii < 4; ii++) {
            float rs = 0.f;
#pragma unroll
            for (int jj = 0; jj < 4; jj++) {
                float p = __expf(acc[ii][jj] - m[ii]);
                Ps[(i0 + ii) * PP + (j0 + jj)] = p;
                rs += p;
            }
#pragma unroll
            for (int off = 8; off; off >>= 1)
                rs += __shfl_xor_sync(0xFFFFFFFFu, rs, off);
            l[ii] = l[ii] * alpha[ii] + rs;
#pragma unroll
            for (int cc = 0; cc < 8; cc++) o[ii][cc] *= alpha[ii];
        }
        __syncthreads();   // Ps visible to all; also keeps Vs valid during PV

        // ---- O += P V ----
#pragma unroll 2
        for (int j = 0; j < BN; j++) {
            float p0 = Ps[(i0 + 0) * PP + j];
            float p1 = Ps[(i0 + 1) * PP + j];
            float p2 = Ps[(i0 + 2) * PP + j];
            float p3 = Ps[(i0 + 3) * PP + j];
            float4 va = *(const float4*)(Vs + j * VP + c0);
            float4 vb = *(const float4*)(Vs + j * VP + c0 + 4);
            o[0][0] += p0 * va.x; o[0][1] += p0 * va.y; o[0][2] += p0 * va.z; o[0][3] += p0 * va.w;
            o[0][4] += p0 * vb.x; o[0][5] += p0 * vb.y; o[0][6] += p0 * vb.z; o[0][7] += p0 * vb.w;
            o[1][0] += p1 * va.x; o[1][1] += p1 * va.y; o[1][2] += p1 * va.z; o[1][3] += p1 * va.w;
            o[1][4] += p1 * vb.x; o[1][5] += p1 * vb.y; o[1][6] += p1 * vb.z; o[1][7] += p1 * vb.w;
            o[2][0] += p2 * va.x; o[2][1] += p2 * va.y; o[2][2] += p2 * va.z; o[2][3] += p2 * va.w;
            o[2][4] += p2 * vb.x; o[2][5] += p2 * vb.y; o[2][6] += p2 * vb.z; o[2][7] += p2 * vb.w;
            o[3][0] += p3 * va.x; o[3][1] += p3 * va.y; o[3][2] += p3 * va.z; o[3][3] += p3 * va.w;
            o[3][4] += p3 * vb.x; o[3][5] += p3 * vb.y; o[3][6] += p3 * vb.z; o[3][7] += p3 * vb.w;
        }
    }

    // epilogue: divide by rowsum and sqrt(2D)
    const float SQRT2D = 11.313708498984761f;
#pragma unroll
    for (int ii = 0; ii < 4; ii++) {
        float sc = 1.0f / (l[ii] * SQRT2D);
        size_t base = ((size_t)bh * S_ + (size_t)qb * BM + i0 + ii) * D2_ + c0;
        float4 a, b4;
        a.x = o[ii][0] * sc; a.y = o[ii][1] * sc; a.z = o[ii][2] * sc; a.w = o[ii][3] * sc;
        b4.x = o[ii][4] * sc; b4.y = o[ii][5] * sc; b4.z = o[ii][6] * sc; b4.w = o[ii][7] * sc;
        *(float4*)(g_O + base)     = a;
        *(float4*)(g_O + base + 4) = b4;
    }
}

// ---------------- kernel 4: masked combine to output -------------------------
// out[b,s,j] = [pairs0==s]*O[b, j/128, s, j%128] + [pairs1==s]*O[b, 4+j/128, s, j%128]
__global__ void combine_kernel(float* __restrict__ out) {
    size_t t = (size_t)blockIdx.x * 256 + threadIdx.x;   // B*S*128 float4s
    if (t >= (size_t)B_ * S_ * 128) return;
    int    j4 = (int)(t & 127);
    size_t bs = t >> 7;
    int    s  = (int)(bs & (S_ - 1));
    int    b  = (int)(bs >> 10);

    int2 pr = g_pairs[bs];
    int hsub = j4 >> 5;           // j/128
    int c    = (j4 & 31) * 4;     // j%128 (float4 aligned)

    float4 r = make_float4(0.f, 0.f, 0.f, 0.f);
    if (pr.x == s) {
        float4 v = *(const float4*)(g_O + (((size_t)b * H_ + hsub) * S_ + s) * D2_ + c);
        r.x += v.x; r.y += v.y; r.z += v.z; r.w += v.w;
    }
    if (pr.y == s) {
        float4 v = *(const float4*)(g_O + (((size_t)b * H_ + 4 + hsub) * S_ + s) * D2_ + c);
        r.x += v.x; r.y += v.y; r.z += v.z; r.w += v.w;
    }
    ((float4*)out)[t] = r;
}

// ---------------- launch -----------------------------------------------------
extern "C" void kernel_launch(void* const* d_in, const int* in_sizes, int n_in,
                              void* d_out, int out_size) {
    const float* Q = (const float*)d_in[0];
    const float* K = (const float*)d_in[1];
    const float* V = (const float*)d_in[2];
    const float* C = (const float*)d_in[3];

    static bool attr_set = false;
    const int smem_bytes = (BM * QP + BN * KP + BN * VP + BM * PP) * (int)sizeof(float);
    if (!attr_set) {
        cudaFuncSetAttribute(attn_kernel, cudaFuncAttributeMaxDynamicSharedMemorySize, smem_bytes);
        attr_set = true;
    }

    pairs_kernel<<<dim3(16, B_), 256>>>(C);

    size_t gthreads = (size_t)B_ * H_ * S_ * 32;
    gather_kernel<<<(unsigned)((gthreads + 255) / 256), 256>>>(Q, K, V);

    attn_kernel<<<dim3(S_ / BM, B_ * H_), 256, smem_bytes>>>();

    size_t cthreads = (size_t)B_ * S_ * 128;
    combine_kernel<<<(unsigned)((cthreads + 255) / 256), 256>>>((float*)d_out);
}

// round 2
// speedup vs baseline: 1.7009x; 1.7009x over previous
#include <cuda_runtime.h>
#include <math.h>

#define B_  16
#define H_  8
#define S_  1024
#define D_  64
#define D2_ 128

// ---------------- scratch (static device globals; no allocation) -------------
__device__ int2  g_pairs[B_ * S_];
__device__ int   g_cnt[B_ * 2];
__device__ int   g_list[B_ * 2 * S_];
__device__ float g_Kc[(size_t)B_ * H_ * S_ * D2_];
__device__ float g_Vc[(size_t)B_ * H_ * S_ * D2_];

// ---------------- kernel 0: zero list counters -------------------------------
__global__ void init_kernel() {
    if (threadIdx.x < B_ * 2) g_cnt[threadIdx.x] = 0;
}

// ---------------- kernel 1: IoU argmax pairs + compacted lists ---------------
// grid: (16, B), block 256 (8 warps, 8 rows/warp)
__global__ void pairs_kernel(const float* __restrict__ centers) {
    __shared__ float sx1[S_], sy1[S_], sx2[S_], sy2[S_], sar[S_], sl1[S_];
    const int b = blockIdx.y;
    const float* c = centers + (size_t)b * S_ * 4;

    for (int i = threadIdx.x; i < S_; i += 256) {
        float cx = c[i * 4 + 0];
        float cy = c[i * 4 + 1];
        float hh = c[i * 4 + 2];   // h is index 2
        float ww = c[i * 4 + 3];   // w is index 3
        float x1 = cx - ww * 0.5f;
        float y1 = cy - hh * 0.5f;
        float x2 = cx + ww * 0.5f;
        float y2 = cy + hh * 0.5f;
        sx1[i] = x1; sy1[i] = y1; sx2[i] = x2; sy2[i] = y2;
        float dx = x2 - x1, dy = y2 - y1;
        sar[i] = dx * dy;                    // area from box diffs (matches ref)
        sl1[i] = fabsf(dx) + fabsf(dy);      // l1 from box diffs (matches ref)
    }
    __syncthreads();

    const int warp = threadIdx.x >> 5;
    const int lane = threadIdx.x & 31;
    const int rowbase = blockIdx.x * 64 + warp * 8;

    for (int r = 0; r < 8; r++) {
        const int i = rowbase + r;
        const float ax1 = sx1[i], ay1 = sy1[i], ax2 = sx2[i], ay2 = sy2[i], aa = sar[i];
        float best = -INFINITY;
        int   bidx = 0;
        for (int k = lane; k < S_; k += 32) {
            float xm = fmaxf(ax1, sx1[k]);
            float ym = fmaxf(ay1, sy1[k]);
            float xM = fminf(ax2, sx2[k]);
            float yM = fminf(ay2, sy2[k]);
            float inter = (xM - xm) * (yM - ym);         // NOT clamped (matches ref)
            float uni   = (aa + sar[k]) - inter;         // (a_i + a_k) - inter order
            float iou   = __fdiv_rn(inter, uni);         // IEEE div regardless of fast_math
            if (k == i) iou -= 1.0f;                     // - eye
            if (iou > best) { best = iou; bidx = k; }    // strict > keeps first occurrence
        }
        // warp argmax reduce; ties -> smaller index (jnp.argmax first-occurrence)
        for (int off = 16; off; off >>= 1) {
            float ov = __shfl_xor_sync(0xFFFFFFFFu, best, off);
            int   oi = __shfl_xor_sync(0xFFFFFFFFu, bidx, off);
            if (ov > best || (ov == best && oi < bidx)) { best = ov; bidx = oi; }
        }
        if (lane == 0) {
            int partner = bidx;
            int2 pr = (sl1[i] >= sl1[partner]) ? make_int2(i, partner)
                                               : make_int2(partner, i);
            g_pairs[b * S_ + i] = pr;
            // compacted work lists: half0 if this row is the "left" member,
            // half1 if the "right" member (both iff partner == i)
            if (pr.x == i) { int p = atomicAdd(&g_cnt[b * 2 + 0], 1); g_list[(b * 2 + 0) * S_ + p] = i; }
            if (pr.y == i) { int p = atomicAdd(&g_cnt[b * 2 + 1], 1); g_list[(b * 2 + 1) * S_ + p] = i; }
        }
    }
}

// ---------------- kernel 2: gather concat k/v --------------------------------
__global__ void gather_kernel(const float* __restrict__ K,
                              const float* __restrict__ V) {
    size_t t = (size_t)blockIdx.x * 256 + threadIdx.x;   // B*H*S*32 total
    if (t >= (size_t)B_ * H_ * S_ * 32) return;
    int    d4  = (int)(t & 31);
    size_t bhs = t >> 5;                 // b*H*S + h*S + s
    int    s   = (int)(bhs & (S_ - 1));
    size_t bh  = bhs >> 10;              // b*H + h
    int    b   = (int)(bh >> 3);

    int2 pr = g_pairs[b * S_ + s];
    int  src = (d4 < 16) ? pr.x : pr.y;
    int  dd  = (d4 & 15) * 4;

    size_t srcoff = (bh * S_ + (size_t)src) * D_ + dd;
    size_t dst    = bhs * D2_ + (size_t)d4 * 4;

    *(float4*)(g_Kc + dst) = *(const float4*)(K + srcoff);
    *(float4*)(g_Vc + dst) = *(const float4*)(V + srcoff);
}

// ---------------- kernel 3: fp32 flash attention on compacted rows -----------
#define BM 64
#define BN 64
#define QP 129   // padded pitches to break bank conflicts
#define KP 129
#define VP 128   // conflict-free for the broadcast float4 pattern
#define PP 65

__global__ __launch_bounds__(256, 2) void attn_kernel(const float* __restrict__ Q,
                                                      float* __restrict__ out) {
    extern __shared__ float sm[];
    float* Qs = sm;                  // BM x QP
    float* Ks = Qs + BM * QP;        // BN x KP
    float* Vs = Ks + BN * KP;        // BN x VP
    float* Ps = Vs + BN * VP;        // BM x PP
    int*   s_row = (int*)(Ps + BM * PP);   // BM
    int*   s_px  = s_row + BM;             // BM
    int*   s_py  = s_px + BM;              // BM

    const int tile = blockIdx.x;     // 0..15 (worst case)
    const int h    = blockIdx.y;     // 0..7
    const int b    = blockIdx.z;     // 0..15
    const int half = h >> 2;

    const int n = g_cnt[b * 2 + half];
    if (tile * BM >= n) return;      // uniform early exit for unused tiles

    const int tid = threadIdx.x;

    // load tile metadata (rows + their pair indices)
    if (tid < BM) {
        int e = tile * BM + tid;
        if (e < n) {
            int s = g_list[(b * 2 + half) * S_ + e];
            int2 pr = g_pairs[b * S_ + s];
            s_row[tid] = s; s_px[tid] = pr.x; s_py[tid] = pr.y;
        } else {
            s_row[tid] = -1; s_px[tid] = 0; s_py[tid] = 0;
        }
    }
    __syncthreads();

    const int bh = b * H_ + h;
    const float* Qh = Q + (size_t)bh * S_ * D_;
    const float* Kg = g_Kc + (size_t)bh * S_ * D2_;
    const float* Vg = g_Vc + (size_t)bh * S_ * D2_;

    // gather Q tile (concat of pair members) straight from global query
    for (int f = tid; f < BM * 32; f += 256) {
        int row = f >> 5, d4 = f & 31;
        int src = (d4 < 16) ? s_px[row] : s_py[row];
        float4 v = *(const float4*)(Qh + (size_t)src * D_ + (d4 & 15) * 4);
        float* p = Qs + row * QP + d4 * 4;
        p[0] = v.x; p[1] = v.y; p[2] = v.z; p[3] = v.w;
    }

    const int tx = tid & 15, ty = tid >> 4;
    const int i0 = ty * 4;           // 4 q-rows per thread
    const int j0 = tx * 4;           // 4 k-cols per thread (for S)
    const int c0 = tx * 8;           // 8 out-cols per thread (for O)

    float m[4], l[4], o[4][8];
#pragma unroll
    for (int ii = 0; ii < 4; ii++) {
        m[ii] = -INFINITY; l[ii] = 0.f;
#pragma unroll
        for (int cc = 0; cc < 8; cc++) o[ii][cc] = 0.f;
    }

    for (int kt = 0; kt < S_ / BN; kt++) {
        __syncthreads();  // guard Ks/Vs/Ps reuse from previous iteration (and Q load at kt=0)
        for (int f = tid; f < BN * 32; f += 256) {
            int row = f >> 5, d4 = f & 31;
            float4 kv = *(const float4*)(Kg + ((size_t)kt * BN + row) * D2_ + d4 * 4);
            float* kp = Ks + row * KP + d4 * 4;
            kp[0] = kv.x; kp[1] = kv.y; kp[2] = kv.z; kp[3] = kv.w;
            float4 vv = *(const float4*)(Vg + ((size_t)kt * BN + row) * D2_ + d4 * 4);
            float* vp = Vs + row * VP + d4 * 4;
            vp[0] = vv.x; vp[1] = vv.y; vp[2] = vv.z; vp[3] = vv.w;
        }
        __syncthreads();

        // ---- S = Q K^T (4x4 microtile) ----
        float acc[4][4];
#pragma unroll
        for (int ii = 0; ii < 4; ii++)
#pragma unroll
            for (int jj = 0; jj < 4; jj++) acc[ii][jj] = 0.f;

#pragma unroll 4
        for (int d = 0; d < D2_; d++) {
            float q0 = Qs[(i0 + 0) * QP + d];
            float q1 = Qs[(i0 + 1) * QP + d];
            float q2 = Qs[(i0 + 2) * QP + d];
            float q3 = Qs[(i0 + 3) * QP + d];
            float k0 = Ks[(j0 + 0) * KP + d];
            float k1 = Ks[(j0 + 1) * KP + d];
            float k2 = Ks[(j0 + 2) * KP + d];
            float k3 = Ks[(j0 + 3) * KP + d];
            acc[0][0] += q0 * k0; acc[0][1] += q0 * k1; acc[0][2] += q0 * k2; acc[0][3] += q0 * k3;
            acc[1][0] += q1 * k0; acc[1][1] += q1 * k1; acc[1][2] += q1 * k2; acc[1][3] += q1 * k3;
            acc[2][0] += q2 * k0; acc[2][1] += q2 * k1; acc[2][2] += q2 * k2; acc[2][3] += q2 * k3;
            acc[3][0] += q3 * k0; acc[3][1] += q3 * k1; acc[3][2] += q3 * k2; acc[3][3] += q3 * k3;
        }

        // ---- online softmax update ----
        float alpha[4];
#pragma unroll
        for (int ii = 0; ii < 4; ii++) {
            float mt = fmaxf(fmaxf(acc[ii][0], acc[ii][1]), fmaxf(acc[ii][2], acc[ii][3]));
#pragma unroll
            for (int off = 8; off; off >>= 1)
                mt = fmaxf(mt, __shfl_xor_sync(0xFFFFFFFFu, mt, off));
            float mn = fmaxf(m[ii], mt);
            alpha[ii] = __expf(m[ii] - mn);   // first tile: exp(-inf)=0
            m[ii] = mn;
        }
#pragma unroll
        for (int ii = 0; ii < 4; ii++) {
            float rs = 0.f;
#pragma unroll
            for (int jj = 0; jj < 4; jj++) {
                float p = __expf(acc[ii][jj] - m[ii]);
                Ps[(i0 + ii) * PP + (j0 + jj)] = p;
                rs += p;
            }
#pragma unroll
            for (int off = 8; off; off >>= 1)
                rs += __shfl_xor_sync(0xFFFFFFFFu, rs, off);
            l[ii] = l[ii] * alpha[ii] + rs;
#pragma unroll
            for (int cc = 0; cc < 8; cc++) o[ii][cc] *= alpha[ii];
        }
        __syncthreads();   // Ps visible to all; also keeps Vs valid during PV

        // ---- O += P V ----
#pragma unroll 2
        for (int j = 0; j < BN; j++) {
            float p0 = Ps[(i0 + 0) * PP + j];
            float p1 = Ps[(i0 + 1) * PP + j];
            float p2 = Ps[(i0 + 2) * PP + j];
            float p3 = Ps[(i0 + 3) * PP + j];
            float4 va = *(const float4*)(Vs + j * VP + c0);
            float4 vb = *(const float4*)(Vs + j * VP + c0 + 4);
            o[0][0] += p0 * va.x; o[0][1] += p0 * va.y; o[0][2] += p0 * va.z; o[0][3] += p0 * va.w;
            o[0][4] += p0 * vb.x; o[0][5] += p0 * vb.y; o[0][6] += p0 * vb.z; o[0][7] += p0 * vb.w;
            o[1][0] += p1 * va.x; o[1][1] += p1 * va.y; o[1][2] += p1 * va.z; o[1][3] += p1 * va.w;
            o[1][4] += p1 * vb.x; o[1][5] += p1 * vb.y; o[1][6] += p1 * vb.z; o[1][7] += p1 * vb.w;
            o[2][0] += p2 * va.x; o[2][1] += p2 * va.y; o[2][2] += p2 * va.z; o[2][3] += p2 * va.w;
            o[2][4] += p2 * vb.x; o[2][5] += p2 * vb.y; o[2][6] += p2 * vb.z; o[2][7] += p2 * vb.w;
            o[3][0] += p3 * va.x; o[3][1] += p3 * va.y; o[3][2] += p3 * va.z; o[3][3] += p3 * va.w;
            o[3][4] += p3 * vb.x; o[3][5] += p3 * vb.y; o[3][6] += p3 * vb.z; o[3][7] += p3 * vb.w;
        }
    }

    // epilogue: divide by rowsum and sqrt(2D); write directly to final output
    // out[b, s, (h&3)*128 + c]  (exactly the kept slice of the reference combine)
    const float SQRT2D = 11.313708498984761f;
    const int hc = (h & 3) * 128 + c0;
#pragma unroll
    for (int ii = 0; ii < 4; ii++) {
        int s = s_row[i0 + ii];
        if (s < 0) continue;                  // padded tail row
        float sc = 1.0f / (l[ii] * SQRT2D);
        float r[8];
#pragma unroll
        for (int cc = 0; cc < 8; cc++) r[cc] = o[ii][cc] * sc;
        float* dst = out + ((size_t)(b * S_ + s)) * 512 + hc;
        bool dup = (s_px[i0 + ii] == s_py[i0 + ii]);   // partner==s: both halves hit same slot
        if (dup) {
#pragma unroll
            for (int cc = 0; cc < 8; cc++) atomicAdd(dst + cc, r[cc]);
        } else {
            float4 a = make_float4(r[0], r[1], r[2], r[3]);
            float4 c4 = make_float4(r[4], r[5], r[6], r[7]);
            *(float4*)(dst)     = a;
            *(float4*)(dst + 4) = c4;
        }
    }
}

// ---------------- launch -----------------------------------------------------
extern "C" void kernel_launch(void* const* d_in, const int* in_sizes, int n_in,
                              void* d_out, int out_size) {
    const float* Q = (const float*)d_in[0];
    const float* K = (const float*)d_in[1];
    const float* V = (const float*)d_in[2];
    const float* C = (const float*)d_in[3];

    const int smem_bytes = (BM * QP + BN * KP + BN * VP + BM * PP) * (int)sizeof(float)
                         + 3 * BM * (int)sizeof(int);
    static bool attr_set = false;
    if (!attr_set) {
        cudaFuncSetAttribute(attn_kernel, cudaFuncAttributeMaxDynamicSharedMemorySize, smem_bytes);
        attr_set = true;
    }

    init_kernel<<<1, 32>>>();
    pairs_kernel<<<dim3(16, B_), 256>>>(C);

    size_t gthreads = (size_t)B_ * H_ * S_ * 32;
    gather_kernel<<<(unsigned)((gthreads + 255) / 256), 256>>>(K, V);

    // zero output (needed for the rare dup rows that accumulate via atomics)
    cudaMemsetAsync(d_out, 0, (size_t)out_size * sizeof(float));

    attn_kernel<<<dim3(S_ / BM, H_, B_), 256, smem_bytes>>>(Q, (float*)d_out);
}

// round 4
// speedup vs baseline: 4.0546x; 2.3838x over previous
#include <cuda_runtime.h>
#include <cuda_bf16.h>
#include <math.h>
#include <stdint.h>

typedef unsigned short u16;

#define B_  16
#define H_  8
#define S_  1024
#define D_  64
#define D2_ 128

// ---------------- scratch (static device globals; no allocation) -------------
__device__ int2 g_pairs[B_ * S_];
__device__ int  g_cnt[B_ * 2];
__device__ int  g_list[B_ * 2 * S_];
__device__ __align__(16) u16 g_Khi[(size_t)B_ * H_ * S_ * D2_];
__device__ __align__(16) u16 g_Klo[(size_t)B_ * H_ * S_ * D2_];
__device__ __align__(16) u16 g_VThi[(size_t)B_ * H_ * D2_ * S_];
__device__ __align__(16) u16 g_VTlo[(size_t)B_ * H_ * D2_ * S_];

// ---------------- helpers ----------------------------------------------------
__device__ __forceinline__ u16 f2bf(float v) {
    __nv_bfloat16 h = __float2bfloat16(v);
    return *(u16*)&h;
}
__device__ __forceinline__ float bf2f(u16 x) {
    __nv_bfloat16 h = *(__nv_bfloat16*)&x;
    return __bfloat162float(h);
}
__device__ __forceinline__ uint32_t smem_u32(const void* p) {
    uint32_t a;
    asm("{ .reg .u64 t; cvta.to.shared.u64 t, %1; cvt.u32.u64 %0, t; }" : "=r"(a) : "l"(p));
    return a;
}
__device__ __forceinline__ void ldsm4(uint32_t* r, uint32_t addr) {
    asm volatile("ldmatrix.sync.aligned.m8n8.x4.shared.b16 {%0,%1,%2,%3}, [%4];"
                 : "=r"(r[0]), "=r"(r[1]), "=r"(r[2]), "=r"(r[3]) : "r"(addr));
}
__device__ __forceinline__ void mma_bf16(float* c, const uint32_t* a, uint32_t b0, uint32_t b1) {
    asm volatile(
        "mma.sync.aligned.m16n8k16.row.col.f32.bf16.bf16.f32 "
        "{%0,%1,%2,%3}, {%4,%5,%6,%7}, {%8,%9}, {%0,%1,%2,%3};"
        : "+f"(c[0]), "+f"(c[1]), "+f"(c[2]), "+f"(c[3])
        : "r"(a[0]), "r"(a[1]), "r"(a[2]), "r"(a[3]), "r"(b0), "r"(b1));
}

// SMEM layout (bytes). Pitches: Q/K rows 272B (136 u16), VT rows 144B (72 u16).
#define SM_QHI 0
#define SM_QLO 34816
#define SM_KHI 69632
#define SM_KLO 87040
#define SM_VHI 104448
#define SM_VLO 122880
#define SM_META 141312
#define SMEM_TOTAL (SM_META + 1536)

// ---------------- kernel 0: zero list counters -------------------------------
__global__ void init_kernel() {
    if (threadIdx.x < B_ * 2) g_cnt[threadIdx.x] = 0;
}

// ---------------- kernel 1: IoU argmax pairs + compacted lists ---------------
__global__ void pairs_kernel(const float* __restrict__ centers) {
    __shared__ float sx1[S_], sy1[S_], sx2[S_], sy2[S_], sar[S_], sl1[S_];
    const int b = blockIdx.y;
    const float* c = centers + (size_t)b * S_ * 4;

    for (int i = threadIdx.x; i < S_; i += 256) {
        float cx = c[i * 4 + 0], cy = c[i * 4 + 1];
        float hh = c[i * 4 + 2], ww = c[i * 4 + 3];
        float x1 = cx - ww * 0.5f, y1 = cy - hh * 0.5f;
        float x2 = cx + ww * 0.5f, y2 = cy + hh * 0.5f;
        sx1[i] = x1; sy1[i] = y1; sx2[i] = x2; sy2[i] = y2;
        float dx = x2 - x1, dy = y2 - y1;
        sar[i] = dx * dy;
        sl1[i] = fabsf(dx) + fabsf(dy);
    }
    __syncthreads();

    const int warp = threadIdx.x >> 5;
    const int lane = threadIdx.x & 31;
    const int rowbase = blockIdx.x * 64 + warp * 8;

    for (int r = 0; r < 8; r++) {
        const int i = rowbase + r;
        const float ax1 = sx1[i], ay1 = sy1[i], ax2 = sx2[i], ay2 = sy2[i], aa = sar[i];
        float best = -INFINITY;
        int bidx = 0;
        for (int k = lane; k < S_; k += 32) {
            float xm = fmaxf(ax1, sx1[k]);
            float ym = fmaxf(ay1, sy1[k]);
            float xM = fminf(ax2, sx2[k]);
            float yM = fminf(ay2, sy2[k]);
            float inter = (xM - xm) * (yM - ym);
            float uni = (aa + sar[k]) - inter;
            float iou = __fdiv_rn(inter, uni);
            if (k == i) iou -= 1.0f;
            if (iou > best) { best = iou; bidx = k; }
        }
        for (int off = 16; off; off >>= 1) {
            float ov = __shfl_xor_sync(0xFFFFFFFFu, best, off);
            int oi = __shfl_xor_sync(0xFFFFFFFFu, bidx, off);
            if (ov > best || (ov == best && oi < bidx)) { best = ov; bidx = oi; }
        }
        if (lane == 0) {
            int partner = bidx;
            int2 pr = (sl1[i] >= sl1[partner]) ? make_int2(i, partner) : make_int2(partner, i);
            g_pairs[b * S_ + i] = pr;
            if (pr.x == i) { int p = atomicAdd(&g_cnt[b * 2 + 0], 1); g_list[(b * 2 + 0) * S_ + p] = i; }
            if (pr.y == i) { int p = atomicAdd(&g_cnt[b * 2 + 1], 1); g_list[(b * 2 + 1) * S_ + p] = i; }
        }
    }
}

// ---------------- kernel 2: gather K concat -> bf16 hi/lo --------------------
__global__ void gatherK_kernel(const float* __restrict__ K) {
    size_t t = (size_t)blockIdx.x * 256 + threadIdx.x;   // B*H*S*16
    if (t >= (size_t)B_ * H_ * S_ * 16) return;
    int d8 = (int)(t & 15);
    size_t bhs = t >> 4;
    int s = (int)(bhs & (S_ - 1));
    size_t bh = bhs >> 10;
    int b = (int)(bh >> 3);
    int2 pr = g_pairs[b * S_ + s];
    int src = (d8 < 8) ? pr.x : pr.y;
    const float* p = K + (bh * S_ + (size_t)src) * D_ + (d8 & 7) * 8;
    float4 a = *(const float4*)p;
    float4 c = *(const float4*)(p + 4);
    float v[8] = {a.x, a.y, a.z, a.w, c.x, c.y, c.z, c.w};
    u16 hi[8], lo[8];
#pragma unroll
    for (int k = 0; k < 8; k++) {
        hi[k] = f2bf(v[k]);
        lo[k] = f2bf(v[k] - bf2f(hi[k]));
    }
    uint4 wh, wl;
    wh.x = hi[0] | ((uint32_t)hi[1] << 16); wh.y = hi[2] | ((uint32_t)hi[3] << 16);
    wh.z = hi[4] | ((uint32_t)hi[5] << 16); wh.w = hi[6] | ((uint32_t)hi[7] << 16);
    wl.x = lo[0] | ((uint32_t)lo[1] << 16); wl.y = lo[2] | ((uint32_t)lo[3] << 16);
    wl.z = lo[4] | ((uint32_t)lo[5] << 16); wl.w = lo[6] | ((uint32_t)lo[7] << 16);
    ((uint4*)g_Khi)[t] = wh;
    ((uint4*)g_Klo)[t] = wl;
}

// ---------------- kernel 3: gather V concat -> transposed bf16 hi/lo ---------
// output layout: g_VT*[bh][c(128)][s(1024)]
__global__ void gatherVT_kernel(const float* __restrict__ V) {
    __shared__ u16 sh[64][136];
    __shared__ u16 sl[64][136];
    const int bh = blockIdx.y;
    const int b = bh >> 3;
    const int s0 = blockIdx.x * 64;
    const int tid = threadIdx.x;

    for (int f = tid; f < 64 * 16; f += 256) {
        int srow = f >> 4, d8 = f & 15;
        int s = s0 + srow;
        int2 pr = g_pairs[b * S_ + s];
        int src = (d8 < 8) ? pr.x : pr.y;
        const float* p = V + ((size_t)bh * S_ + src) * D_ + (d8 & 7) * 8;
        float4 a = *(const float4*)p;
        float4 c = *(const float4*)(p + 4);
        float v[8] = {a.x, a.y, a.z, a.w, c.x, c.y, c.z, c.w};
#pragma unroll
        for (int k = 0; k < 8; k++) {
            u16 h = f2bf(v[k]);
            sh[srow][d8 * 8 + k] = h;
            sl[srow][d8 * 8 + k] = f2bf(v[k] - bf2f(h));
        }
    }
    __syncthreads();

    for (int f = tid; f < 128 * 16; f += 256) {
        int c = f >> 4, s4 = f & 15;
        uint2 wh, wl;
        wh.x = sh[s4 * 4 + 0][c] | ((uint32_t)sh[s4 * 4 + 1][c] << 16);
        wh.y = sh[s4 * 4 + 2][c] | ((uint32_t)sh[s4 * 4 + 3][c] << 16);
        wl.x = sl[s4 * 4 + 0][c] | ((uint32_t)sl[s4 * 4 + 1][c] << 16);
        wl.y = sl[s4 * 4 + 2][c] | ((uint32_t)sl[s4 * 4 + 3][c] << 16);
        size_t idx = ((size_t)bh * 128 + c) * 1024 + s0 + s4 * 4;   // u16 index
        *(uint2*)&g_VThi[idx] = wh;
        *(uint2*)&g_VTlo[idx] = wl;
    }
}

// ---------------- kernel 4: HMMA (mma.sync bf16) flash attention -------------
// CTA: 256 threads / 8 warps, M=128 rows (16 per warp), BN=64 keys per chunk.
__global__ __launch_bounds__(256, 1) void attn_kernel(const float* __restrict__ Q,
                                                      float* __restrict__ out) {
    extern __shared__ char smem[];
    const uint32_t smb = smem_u32(smem);
    const int tile = blockIdx.x;
    const int h = blockIdx.y;
    const int b = blockIdx.z;
    const int half = h >> 2;

    const int n = g_cnt[b * 2 + half];
    if (tile * 128 >= n) return;

    const int tid = threadIdx.x;
    const int wid = tid >> 5;
    const int lane = tid & 31;
    const int m0 = wid * 16;

    int* s_row = (int*)(smem + SM_META);
    int* s_px = s_row + 128;
    int* s_py = s_px + 128;

    if (tid < 128) {
        int e = tile * 128 + tid;
        if (e < n) {
            int s = g_list[(b * 2 + half) * S_ + e];
            int2 pr = g_pairs[b * S_ + s];
            s_row[tid] = s; s_px[tid] = pr.x; s_py[tid] = pr.y;
        } else {
            s_row[tid] = -1; s_px[tid] = 0; s_py[tid] = 0;
        }
    }
    __syncthreads();

    const int bh = b * H_ + h;
    const float* Qh = Q + (size_t)bh * S_ * D_;

    // ---- gather Q tile -> smem hi/lo (pitch 272B) ----
    for (int f = tid; f < 2048; f += 256) {
        int row = f >> 4, d8 = f & 15;
        int src = (d8 < 8) ? s_px[row] : s_py[row];
        const float* p = Qh + (size_t)src * D_ + (d8 & 7) * 8;
        float4 a = *(const float4*)p;
        float4 c = *(const float4*)(p + 4);
        float v[8] = {a.x, a.y, a.z, a.w, c.x, c.y, c.z, c.w};
        u16 hi[8], lo[8];
#pragma unroll
        for (int k = 0; k < 8; k++) {
            hi[k] = f2bf(v[k]);
            lo[k] = f2bf(v[k] - bf2f(hi[k]));
        }
        uint4 wh, wl;
        wh.x = hi[0] | ((uint32_t)hi[1] << 16); wh.y = hi[2] | ((uint32_t)hi[3] << 16);
        wh.z = hi[4] | ((uint32_t)hi[5] << 16); wh.w = hi[6] | ((uint32_t)hi[7] << 16);
        wl.x = lo[0] | ((uint32_t)lo[1] << 16); wl.y = lo[2] | ((uint32_t)lo[3] << 16);
        wl.z = lo[4] | ((uint32_t)lo[5] << 16); wl.w = lo[6] | ((uint32_t)lo[7] << 16);
        *(uint4*)(smem + SM_QHI + row * 272 + d8 * 16) = wh;
        *(uint4*)(smem + SM_QLO + row * 272 + d8 * 16) = wl;
    }

    // ldmatrix lane addressing
    // A (Q, m16k16): row = m0 + (lane&15), colByte = (lane>>4)*16 (+k*32)
    const uint32_t aq = smb + SM_QHI + (uint32_t)(m0 + (lane & 15)) * 272 + (uint32_t)(lane >> 4) * 16;
    // B (K / VT, two n-tiles per x4): row = base + (lane&7) + ((lane>>4)<<3),
    //                                 colByte = ((lane>>3)&1)*16 (+k*32)
    const uint32_t brow = (uint32_t)((lane & 7) + ((lane >> 4) << 3));
    const uint32_t bcol = (uint32_t)(((lane >> 3) & 1) * 16);
    const uint32_t ak = smb + SM_KHI + brow * 272 + bcol;
    const uint32_t av = smb + SM_VHI + brow * 144 + bcol;

    const uint4* Kh4 = (const uint4*)g_Khi;
    const uint4* Kl4 = (const uint4*)g_Klo;
    const uint4* Vh4 = (const uint4*)g_VThi;
    const uint4* Vl4 = (const uint4*)g_VTlo;

    float oacc[16][4];
#pragma unroll
    for (int i = 0; i < 16; i++)
#pragma unroll
        for (int j = 0; j < 4; j++) oacc[i][j] = 0.f;
    float l0 = 0.f, l1 = 0.f;

    for (int kt = 0; kt < 16; kt++) {
        __syncthreads();   // previous chunk's reads of K/V smem done
        // ---- fill K tile (64 x 128, hi/lo) ----
        for (int f = tid; f < 1024; f += 256) {
            int row = f >> 4, d8 = f & 15;
            size_t gi = ((size_t)bh * S_ + (size_t)kt * 64 + row) * 16 + d8;
            *(uint4*)(smem + SM_KHI + row * 272 + d8 * 16) = Kh4[gi];
            *(uint4*)(smem + SM_KLO + row * 272 + d8 * 16) = Kl4[gi];
        }
        // ---- fill VT tile (128 x 64, hi/lo) ----
        for (int f = tid; f < 1024; f += 256) {
            int c = f >> 3, j8 = f & 7;
            size_t gi = ((size_t)bh * 128 + c) * 128 + (size_t)kt * 8 + j8;
            *(uint4*)(smem + SM_VHI + c * 144 + j8 * 16) = Vh4[gi];
            *(uint4*)(smem + SM_VLO + c * 144 + j8 * 16) = Vl4[gi];
        }
        __syncthreads();

        // ---- S = Qhi*Khi + Qlo*Khi + Qhi*Klo ----
        float sacc[8][4];
#pragma unroll
        for (int i = 0; i < 8; i++)
#pragma unroll
            for (int j = 0; j < 4; j++) sacc[i][j] = 0.f;

#pragma unroll
        for (int k = 0; k < 8; k++) {
            uint32_t qh[4], ql[4];
            ldsm4(qh, aq + k * 32);
            ldsm4(ql, aq + 34816 + k * 32);
#pragma unroll
            for (int p = 0; p < 4; p++) {
                uint32_t kh[4], kl[4];
                ldsm4(kh, ak + p * (16 * 272) + k * 32);
                ldsm4(kl, ak + 17408 + p * (16 * 272) + k * 32);
                mma_bf16(sacc[2 * p],     qh, kh[0], kh[1]);
                mma_bf16(sacc[2 * p],     ql, kh[0], kh[1]);
                mma_bf16(sacc[2 * p],     qh, kl[0], kl[1]);
                mma_bf16(sacc[2 * p + 1], qh, kh[2], kh[3]);
                mma_bf16(sacc[2 * p + 1], ql, kh[2], kh[3]);
                mma_bf16(sacc[2 * p + 1], qh, kl[2], kl[3]);
            }
        }

        // ---- P = exp(S) in registers, split hi/lo, build A-fragments ----
        uint32_t phi[4][4], plo[4][4];
#pragma unroll
        for (int nt = 0; nt < 8; nt++) {
            float e0 = __expf(sacc[nt][0]);
            float e1 = __expf(sacc[nt][1]);
            float e2 = __expf(sacc[nt][2]);
            float e3 = __expf(sacc[nt][3]);
            l0 += e0 + e1;
            l1 += e2 + e3;
            u16 h0 = f2bf(e0), h1 = f2bf(e1), h2 = f2bf(e2), h3 = f2bf(e3);
            int kk = nt >> 1, o = (nt & 1) * 2;
            phi[kk][o]     = h0 | ((uint32_t)h1 << 16);
            phi[kk][o + 1] = h2 | ((uint32_t)h3 << 16);
            plo[kk][o]     = f2bf(e0 - bf2f(h0)) | ((uint32_t)f2bf(e1 - bf2f(h1)) << 16);
            plo[kk][o + 1] = f2bf(e2 - bf2f(h2)) | ((uint32_t)f2bf(e3 - bf2f(h3)) << 16);
        }

        // ---- O += Phi*Vhi + Plo*Vhi + Phi*Vlo ----
#pragma unroll
        for (int kk = 0; kk < 4; kk++) {
#pragma unroll
            for (int p = 0; p < 8; p++) {
                uint32_t vh[4], vl[4];
                ldsm4(vh, av + p * (16 * 144) + kk * 32);
                ldsm4(vl, av + 18432 + p * (16 * 144) + kk * 32);
                mma_bf16(oacc[2 * p],     phi[kk], vh[0], vh[1]);
                mma_bf16(oacc[2 * p],     plo[kk], vh[0], vh[1]);
                mma_bf16(oacc[2 * p],     phi[kk], vl[0], vl[1]);
                mma_bf16(oacc[2 * p + 1], phi[kk], vh[2], vh[3]);
                mma_bf16(oacc[2 * p + 1], plo[kk], vh[2], vh[3]);
                mma_bf16(oacc[2 * p + 1], phi[kk], vl[2], vl[3]);
            }
        }
    }

    // ---- epilogue ----
    l0 += __shfl_xor_sync(0xFFFFFFFFu, l0, 1);
    l0 += __shfl_xor_sync(0xFFFFFFFFu, l0, 2);
    l1 += __shfl_xor_sync(0xFFFFFFFFu, l1, 1);
    l1 += __shfl_xor_sync(0xFFFFFFFFu, l1, 2);

    const float SQRT2D = 11.313708498984761f;
    const int r = lane >> 2, cq = lane & 3;
    const int hc = (h & 3) * 128;

#pragma unroll
    for (int hrow = 0; hrow < 2; hrow++) {
        int mrow = m0 + r + hrow * 8;
        int s = s_row[mrow];
        if (s < 0) continue;
        float sc = 1.0f / ((hrow ? l1 : l0) * SQRT2D);
        float* dst = out + ((size_t)(b * S_ + s)) * 512 + hc + cq * 2;
        bool dup = (s_px[mrow] == s_py[mrow]);
#pragma unroll
        for (int nt = 0; nt < 16; nt++) {
            float va = oacc[nt][hrow * 2 + 0] * sc;
            float vb = oacc[nt][hrow * 2 + 1] * sc;
            float* d = dst + nt * 8;
            if (dup) {
                atomicAdd(d + 0, va);
                atomicAdd(d + 1, vb);
            } else {
                *(float2*)d = make_float2(va, vb);
            }
        }
    }
}

// ---------------- launch -----------------------------------------------------
extern "C" void kernel_launch(void* const* d_in, const int* in_sizes, int n_in,
                              void* d_out, int out_size) {
    const float* Q = (const float*)d_in[0];
    const float* K = (const float*)d_in[1];
    const float* V = (const float*)d_in[2];
    const float* C = (const float*)d_in[3];

    static bool attr_set = false;
    if (!attr_set) {
        cudaFuncSetAttribute(attn_kernel, cudaFuncAttributeMaxDynamicSharedMemorySize, SMEM_TOTAL);
        attr_set = true;
    }

    init_kernel<<<1, 32>>>();
    pairs_kernel<<<dim3(16, B_), 256>>>(C);

    size_t kthreads = (size_t)B_ * H_ * S_ * 16;
    gatherK_kernel<<<(unsigned)((kthreads + 255) / 256), 256>>>(K);
    gatherVT_kernel<<<dim3(S_ / 64, B_ * H_), 256>>>(V);

    cudaMemsetAsync(d_out, 0, (size_t)out_size * sizeof(float));

    attn_kernel<<<dim3(8, H_, B_), 256, SMEM_TOTAL>>>(Q, (float*)d_out);
}